// round 3
// baseline (speedup 1.0000x reference)
#include <cuda_runtime.h>
#include <cstdint>

#define USER_NUM 100000
#define ITEM_NUM 50000
#define NODES    150000            // USER_NUM + ITEM_NUM
#define D        256
#define D4       64                // D / 4 (float4 per row)
#define NNZ      6400000
#define BATCH    16384

// ---------------------------------------------------------------------------
// Static device scratch (no allocation allowed)
// ---------------------------------------------------------------------------
__device__ float d_bufA[(size_t)NODES * D];
__device__ float d_bufB[(size_t)NODES * D];
__device__ float d_acc [(size_t)NODES * D];

__device__ int   d_counts[NODES + 1];
__device__ int   d_rowptr[NODES + 1];
__device__ int   d_fill  [NODES + 1];
__device__ int   d_ecol  [NNZ];
__device__ float d_eval  [NNZ];

// ---------------------------------------------------------------------------
// CSR build
// ---------------------------------------------------------------------------
__global__ void k_zero_counts() {
    int i = blockIdx.x * blockDim.x + threadIdx.x;
    if (i <= NODES) d_counts[i] = 0;
}

__global__ void k_histogram(const int* __restrict__ rows) {
    int e = blockIdx.x * blockDim.x + threadIdx.x;
    if (e < NNZ) atomicAdd(&d_counts[rows[e]], 1);
}

// Single-block exclusive scan over d_counts[0..NODES) -> d_rowptr / d_fill
__global__ __launch_bounds__(1024) void k_scan() {
    __shared__ int warp_sums[32];
    const int tid  = threadIdx.x;
    const int lane = tid & 31;
    const int wid  = tid >> 5;
    int carry = 0;
    for (int base = 0; base < NODES; base += 1024) {
        int i = base + tid;
        int v = (i < NODES) ? d_counts[i] : 0;
        // inclusive warp scan
        int x = v;
        #pragma unroll
        for (int o = 1; o < 32; o <<= 1) {
            int y = __shfl_up_sync(0xFFFFFFFFu, x, o);
            if (lane >= o) x += y;
        }
        if (lane == 31) warp_sums[wid] = x;
        __syncthreads();
        if (tid < 32) {
            int w = warp_sums[tid];
            #pragma unroll
            for (int o = 1; o < 32; o <<= 1) {
                int y = __shfl_up_sync(0xFFFFFFFFu, w, o);
                if (tid >= o) w += y;
            }
            warp_sums[tid] = w;
        }
        __syncthreads();
        int warp_off = (wid > 0) ? warp_sums[wid - 1] : 0;
        int excl = carry + warp_off + (x - v);
        if (i < NODES) {
            d_rowptr[i] = excl;
            d_fill[i]   = excl;
        }
        carry += warp_sums[31];
        __syncthreads();   // protect warp_sums before next chunk
    }
    if (tid == 0) d_rowptr[NODES] = carry;
}

__global__ void k_scatter(const int* __restrict__ rows,
                          const int* __restrict__ cols,
                          const float* __restrict__ vals) {
    int e = blockIdx.x * blockDim.x + threadIdx.x;
    if (e < NNZ) {
        int r = rows[e];
        int p = atomicAdd(&d_fill[r], 1);
        d_ecol[p] = cols[e];
        d_eval[p] = vals[e];
    }
}

// ---------------------------------------------------------------------------
// Init: emb = concat(user_emb, item_emb); acc = emb; bufA = emb
// ---------------------------------------------------------------------------
__global__ void k_init(const float4* __restrict__ user_emb,
                       const float4* __restrict__ item_emb) {
    size_t i = (size_t)blockIdx.x * blockDim.x + threadIdx.x;   // float4 index
    const size_t total = (size_t)NODES * D4;
    if (i >= total) return;
    const size_t user_f4 = (size_t)USER_NUM * D4;
    float4 v = (i < user_f4) ? __ldg(user_emb + i) : __ldg(item_emb + (i - user_f4));
    ((float4*)d_bufA)[i] = v;
    ((float4*)d_acc)[i]  = v;
}

// ---------------------------------------------------------------------------
// SpMM: out[r] = sum_e val[e] * in[col[e]] for CSR row r; acc[r] += out[r]
// One warp per row; lane owns float4 idx {lane, lane+32}.
// DIR=0: A->B, DIR=1: B->A (symbols referenced directly).
// ---------------------------------------------------------------------------
__device__ __forceinline__ void fma4(float4& a, float w, const float4& v) {
    a.x = fmaf(w, v.x, a.x);
    a.y = fmaf(w, v.y, a.y);
    a.z = fmaf(w, v.z, a.z);
    a.w = fmaf(w, v.w, a.w);
}

template <int DIR>
__global__ __launch_bounds__(256) void k_spmm() {
    const float4* __restrict__ in4 =
        (const float4*)((DIR == 0) ? d_bufA : d_bufB);
    float4* __restrict__ out4base =
        (float4*)((DIR == 0) ? d_bufB : d_bufA);

    int row = blockIdx.x * 8 + (threadIdx.x >> 5);
    if (row >= NODES) return;
    const int lane = threadIdx.x & 31;
    const int s = d_rowptr[row];
    const int e = d_rowptr[row + 1];

    float4 a0 = make_float4(0.f, 0.f, 0.f, 0.f);
    float4 a1 = make_float4(0.f, 0.f, 0.f, 0.f);

    int k = s;
    // 4-edge unroll: 8 independent 512B gather loads in flight (MLP=8)
    for (; k + 4 <= e; k += 4) {
        int   c0 = __ldg(d_ecol + k),     c1 = __ldg(d_ecol + k + 1);
        int   c2 = __ldg(d_ecol + k + 2), c3 = __ldg(d_ecol + k + 3);
        float w0 = __ldg(d_eval + k),     w1 = __ldg(d_eval + k + 1);
        float w2 = __ldg(d_eval + k + 2), w3 = __ldg(d_eval + k + 3);
        const float4* p0 = in4 + (size_t)c0 * D4 + lane;
        const float4* p1 = in4 + (size_t)c1 * D4 + lane;
        const float4* p2 = in4 + (size_t)c2 * D4 + lane;
        const float4* p3 = in4 + (size_t)c3 * D4 + lane;
        float4 x0 = p0[0], x1 = p0[32];
        float4 y0 = p1[0], y1 = p1[32];
        float4 z0 = p2[0], z1 = p2[32];
        float4 v0 = p3[0], v1 = p3[32];
        fma4(a0, w0, x0); fma4(a1, w0, x1);
        fma4(a0, w1, y0); fma4(a1, w1, y1);
        fma4(a0, w2, z0); fma4(a1, w2, z1);
        fma4(a0, w3, v0); fma4(a1, w3, v1);
    }
    for (; k < e; ++k) {
        int   c0 = __ldg(d_ecol + k);
        float w0 = __ldg(d_eval + k);
        const float4* p0 = in4 + (size_t)c0 * D4 + lane;
        float4 x0 = p0[0], x1 = p0[32];
        fma4(a0, w0, x0);
        fma4(a1, w0, x1);
    }

    float4* out4 = out4base + (size_t)row * D4 + lane;
    out4[0]  = a0;
    out4[32] = a1;

    float4* acc4 = (float4*)d_acc + (size_t)row * D4 + lane;
    float4 c0 = acc4[0];
    float4 c1 = acc4[32];
    c0.x += a0.x; c0.y += a0.y; c0.z += a0.z; c0.w += a0.w;
    c1.x += a1.x; c1.y += a1.y; c1.z += a1.z; c1.w += a1.w;
    acc4[0]  = c0;
    acc4[32] = c1;
}

// ---------------------------------------------------------------------------
// Readout: gamma[b] = dot(acc[users[b]], acc[USER_NUM + items[b]]) / 16
// ---------------------------------------------------------------------------
__global__ __launch_bounds__(256) void k_dot(const int* __restrict__ users,
                                             const int* __restrict__ items,
                                             float* __restrict__ gamma) {
    int b = blockIdx.x * 8 + (threadIdx.x >> 5);
    if (b >= BATCH) return;
    const int lane = threadIdx.x & 31;
    int u  = __ldg(users + b);
    int it = USER_NUM + __ldg(items + b);

    const float4* pu = (const float4*)d_acc + (size_t)u  * D4 + lane;
    const float4* pi = (const float4*)d_acc + (size_t)it * D4 + lane;
    float4 u0 = pu[0],  u1 = pu[32];
    float4 i0 = pi[0],  i1 = pi[32];

    float s = u0.x * i0.x + u0.y * i0.y + u0.z * i0.z + u0.w * i0.w
            + u1.x * i1.x + u1.y * i1.y + u1.z * i1.z + u1.w * i1.w;
    #pragma unroll
    for (int o = 16; o > 0; o >>= 1)
        s += __shfl_down_sync(0xFFFFFFFFu, s, o);
    if (lane == 0) gamma[b] = s * (1.0f / 16.0f);   // (1/4)^2 from both means
}

// ---------------------------------------------------------------------------
// Launch
// ---------------------------------------------------------------------------
extern "C" void kernel_launch(void* const* d_in, const int* in_sizes, int n_in,
                              void* d_out, int out_size) {
    const float* user_emb = (const float*)d_in[0];   // [100000, 256]
    const float* item_emb = (const float*)d_in[1];   // [50000, 256]
    const float* vals     = (const float*)d_in[2];   // [NNZ]
    const int*   rows     = (const int*)  d_in[3];   // [NNZ]
    const int*   cols     = (const int*)  d_in[4];   // [NNZ]
    const int*   users    = (const int*)  d_in[5];   // [BATCH]
    const int*   items    = (const int*)  d_in[6];   // [BATCH]
    float*       gamma    = (float*)d_out;           // [BATCH]

    // 1) CSR build
    k_zero_counts<<<(NODES + 256) / 256, 256>>>();
    k_histogram<<<(NNZ + 255) / 256, 256>>>(rows);
    k_scan<<<1, 1024>>>();
    k_scatter<<<(NNZ + 255) / 256, 256>>>(rows, cols, vals);

    // 2) init acc/cur with concatenated embeddings
    {
        size_t total = (size_t)NODES * D4;
        k_init<<<(unsigned)((total + 255) / 256), 256>>>(
            (const float4*)user_emb, (const float4*)item_emb);
    }

    // 3) three propagation layers (ping-pong), acc fused into SpMM
    const int spmm_blocks = (NODES + 7) / 8;
    k_spmm<0><<<spmm_blocks, 256>>>();   // layer 1: A -> B
    k_spmm<1><<<spmm_blocks, 256>>>();   // layer 2: B -> A
    k_spmm<0><<<spmm_blocks, 256>>>();   // layer 3: A -> B

    // 4) readout
    k_dot<<<(BATCH + 7) / 8, 256>>>(users, items, gamma);
}

// round 5
// speedup vs baseline: 1.7071x; 1.7071x over previous
#include <cuda_runtime.h>
#include <cuda_fp16.h>
#include <cstdint>

#define USER_NUM 100000
#define ITEM_NUM 50000
#define NODES    150000            // USER_NUM + ITEM_NUM
#define D        256
#define NNZ      6400000
#define BATCH    16384

// ---------------------------------------------------------------------------
// Static device scratch (no allocation allowed)
// bufA/bufB: half-precision propagation buffers (512B/row) — gather traffic
// halved and the 76.8MB working set fits in L2. acc stays fp32.
// ---------------------------------------------------------------------------
__device__ __align__(16) __half d_bufA[(size_t)NODES * D];
__device__ __align__(16) __half d_bufB[(size_t)NODES * D];
__device__ float d_acc[(size_t)NODES * D];

__device__ int  d_counts[NODES + 1];
__device__ int  d_rowptr[NODES + 1];
__device__ int  d_fill  [NODES + 1];
__device__ int2 d_edges [NNZ];          // .x = col, .y = val (float bits)

// ---------------------------------------------------------------------------
// CSR build
// ---------------------------------------------------------------------------
__global__ void k_zero_counts() {
    int i = blockIdx.x * blockDim.x + threadIdx.x;
    if (i <= NODES) d_counts[i] = 0;
}

__global__ void k_histogram(const int* __restrict__ rows) {
    int e = blockIdx.x * blockDim.x + threadIdx.x;
    if (e < NNZ) atomicAdd(&d_counts[rows[e]], 1);
}

// Single-block exclusive scan over d_counts[0..NODES) -> d_rowptr / d_fill
__global__ __launch_bounds__(1024) void k_scan() {
    __shared__ int warp_sums[32];
    const int tid  = threadIdx.x;
    const int lane = tid & 31;
    const int wid  = tid >> 5;
    int carry = 0;
    for (int base = 0; base < NODES; base += 1024) {
        int i = base + tid;
        int v = (i < NODES) ? d_counts[i] : 0;
        int x = v;
        #pragma unroll
        for (int o = 1; o < 32; o <<= 1) {
            int y = __shfl_up_sync(0xFFFFFFFFu, x, o);
            if (lane >= o) x += y;
        }
        if (lane == 31) warp_sums[wid] = x;
        __syncthreads();
        if (tid < 32) {
            int w = warp_sums[tid];
            #pragma unroll
            for (int o = 1; o < 32; o <<= 1) {
                int y = __shfl_up_sync(0xFFFFFFFFu, w, o);
                if (tid >= o) w += y;
            }
            warp_sums[tid] = w;
        }
        __syncthreads();
        int warp_off = (wid > 0) ? warp_sums[wid - 1] : 0;
        int excl = carry + warp_off + (x - v);
        if (i < NODES) {
            d_rowptr[i] = excl;
            d_fill[i]   = excl;
        }
        carry += warp_sums[31];
        __syncthreads();
    }
    if (tid == 0) d_rowptr[NODES] = carry;
}

__global__ void k_scatter(const int* __restrict__ rows,
                          const int* __restrict__ cols,
                          const float* __restrict__ vals) {
    int e = blockIdx.x * blockDim.x + threadIdx.x;
    if (e < NNZ) {
        int r = rows[e];
        int p = atomicAdd(&d_fill[r], 1);
        d_edges[p] = make_int2(cols[e], __float_as_int(vals[e]));
    }
}

// ---------------------------------------------------------------------------
// Init: acc = concat(user_emb, item_emb) (fp32); bufA = same in half.
// Each thread handles an 8-float chunk (2 x float4 in, 1 x uint4 halves out).
// ---------------------------------------------------------------------------
__global__ void k_init(const float4* __restrict__ user_emb,
                       const float4* __restrict__ item_emb) {
    size_t i = (size_t)blockIdx.x * blockDim.x + threadIdx.x;  // 8-dim chunk
    const size_t total = (size_t)NODES * (D / 8);
    if (i >= total) return;
    size_t f4 = i * 2;
    const size_t user_f4 = (size_t)USER_NUM * (D / 4);
    // chunk never straddles the user/item boundary (row-aligned)
    float4 a, b;
    if (f4 < user_f4) { a = __ldg(user_emb + f4); b = __ldg(user_emb + f4 + 1); }
    else              { a = __ldg(item_emb + f4 - user_f4);
                        b = __ldg(item_emb + f4 + 1 - user_f4); }
    ((float4*)d_acc)[f4]     = a;
    ((float4*)d_acc)[f4 + 1] = b;
    uint4 o;
    __half2 h;
    h = __floats2half2_rn(a.x, a.y); o.x = *(unsigned*)&h;
    h = __floats2half2_rn(a.z, a.w); o.y = *(unsigned*)&h;
    h = __floats2half2_rn(b.x, b.y); o.z = *(unsigned*)&h;
    h = __floats2half2_rn(b.z, b.w); o.w = *(unsigned*)&h;
    ((uint4*)d_bufA)[i] = o;
}

// ---------------------------------------------------------------------------
// SpMM: out[r] = sum_e val[e] * in[col[e]]; acc[r] += out[r]
// Warp per row; lane owns dims [lane*8, lane*8+8). One LDG.128 of halves per
// edge per lane; fp32 accumulation. LAST layer skips writing out.
// ---------------------------------------------------------------------------
__device__ __forceinline__ void accum8(float* a, float w, uint4 v) {
    float2 f;
    f = __half22float2(*reinterpret_cast<__half2*>(&v.x));
    a[0] = fmaf(w, f.x, a[0]); a[1] = fmaf(w, f.y, a[1]);
    f = __half22float2(*reinterpret_cast<__half2*>(&v.y));
    a[2] = fmaf(w, f.x, a[2]); a[3] = fmaf(w, f.y, a[3]);
    f = __half22float2(*reinterpret_cast<__half2*>(&v.z));
    a[4] = fmaf(w, f.x, a[4]); a[5] = fmaf(w, f.y, a[5]);
    f = __half22float2(*reinterpret_cast<__half2*>(&v.w));
    a[6] = fmaf(w, f.x, a[6]); a[7] = fmaf(w, f.y, a[7]);
}

template <int DIR, bool LAST>
__global__ __launch_bounds__(256) void k_spmm() {
    const uint4* __restrict__ inb  = (const uint4*)((DIR == 0) ? d_bufA : d_bufB);
    uint4*       __restrict__ outb = (uint4*)((DIR == 0) ? d_bufB : d_bufA);

    int row = blockIdx.x * 8 + (threadIdx.x >> 5);
    if (row >= NODES) return;
    const int lane = threadIdx.x & 31;
    const int s = d_rowptr[row];
    const int e = d_rowptr[row + 1];

    float a[8] = {0.f, 0.f, 0.f, 0.f, 0.f, 0.f, 0.f, 0.f};

    int k = s;
    // 4-edge unroll: 4 independent 512B gathers in flight per warp
    for (; k + 4 <= e; k += 4) {
        int2 e0 = __ldg(&d_edges[k]);
        int2 e1 = __ldg(&d_edges[k + 1]);
        int2 e2 = __ldg(&d_edges[k + 2]);
        int2 e3 = __ldg(&d_edges[k + 3]);
        uint4 v0 = __ldg(inb + (size_t)e0.x * 32 + lane);
        uint4 v1 = __ldg(inb + (size_t)e1.x * 32 + lane);
        uint4 v2 = __ldg(inb + (size_t)e2.x * 32 + lane);
        uint4 v3 = __ldg(inb + (size_t)e3.x * 32 + lane);
        accum8(a, __int_as_float(e0.y), v0);
        accum8(a, __int_as_float(e1.y), v1);
        accum8(a, __int_as_float(e2.y), v2);
        accum8(a, __int_as_float(e3.y), v3);
    }
    for (; k < e; ++k) {
        int2 e0 = __ldg(&d_edges[k]);
        uint4 v0 = __ldg(inb + (size_t)e0.x * 32 + lane);
        accum8(a, __int_as_float(e0.y), v0);
    }

    // acc += result (fp32). Lane owns float4 indices {2*lane, 2*lane+1}.
    float4* accp = (float4*)d_acc + (size_t)row * 64 + lane * 2;
    float4 c0 = accp[0];
    float4 c1 = accp[1];
    c0.x += a[0]; c0.y += a[1]; c0.z += a[2]; c0.w += a[3];
    c1.x += a[4]; c1.y += a[5]; c1.z += a[6]; c1.w += a[7];
    accp[0] = c0;
    accp[1] = c1;

    if (!LAST) {
        uint4 o;
        __half2 h;
        h = __floats2half2_rn(a[0], a[1]); o.x = *(unsigned*)&h;
        h = __floats2half2_rn(a[2], a[3]); o.y = *(unsigned*)&h;
        h = __floats2half2_rn(a[4], a[5]); o.z = *(unsigned*)&h;
        h = __floats2half2_rn(a[6], a[7]); o.w = *(unsigned*)&h;
        outb[(size_t)row * 32 + lane] = o;
    }
}

// ---------------------------------------------------------------------------
// Readout: gamma[b] = dot(acc[users[b]], acc[USER_NUM + items[b]]) / 16
// ---------------------------------------------------------------------------
__global__ __launch_bounds__(256) void k_dot(const int* __restrict__ users,
                                             const int* __restrict__ items,
                                             float* __restrict__ gamma) {
    int b = blockIdx.x * 8 + (threadIdx.x >> 5);
    if (b >= BATCH) return;
    const int lane = threadIdx.x & 31;
    int u  = __ldg(users + b);
    int it = USER_NUM + __ldg(items + b);

    const float4* pu = (const float4*)d_acc + (size_t)u  * 64 + lane * 2;
    const float4* pi = (const float4*)d_acc + (size_t)it * 64 + lane * 2;
    float4 u0 = pu[0], u1 = pu[1];
    float4 i0 = pi[0], i1 = pi[1];

    float s = u0.x * i0.x + u0.y * i0.y + u0.z * i0.z + u0.w * i0.w
            + u1.x * i1.x + u1.y * i1.y + u1.z * i1.z + u1.w * i1.w;
    #pragma unroll
    for (int o = 16; o > 0; o >>= 1)
        s += __shfl_down_sync(0xFFFFFFFFu, s, o);
    if (lane == 0) gamma[b] = s * (1.0f / 16.0f);   // (1/4)^2 from both means
}

// ---------------------------------------------------------------------------
// Launch
// ---------------------------------------------------------------------------
extern "C" void kernel_launch(void* const* d_in, const int* in_sizes, int n_in,
                              void* d_out, int out_size) {
    const float* user_emb = (const float*)d_in[0];   // [100000, 256]
    const float* item_emb = (const float*)d_in[1];   // [50000, 256]
    const float* vals     = (const float*)d_in[2];   // [NNZ]
    const int*   rows     = (const int*)  d_in[3];   // [NNZ]
    const int*   cols     = (const int*)  d_in[4];   // [NNZ]
    const int*   users    = (const int*)  d_in[5];   // [BATCH]
    const int*   items    = (const int*)  d_in[6];   // [BATCH]
    float*       gamma    = (float*)d_out;           // [BATCH]

    // 1) CSR build
    k_zero_counts<<<(NODES + 256) / 256, 256>>>();
    k_histogram<<<(NNZ + 255) / 256, 256>>>(rows);
    k_scan<<<1, 1024>>>();
    k_scatter<<<(NNZ + 255) / 256, 256>>>(rows, cols, vals);

    // 2) init acc (fp32) + bufA (half)
    {
        size_t total = (size_t)NODES * (D / 8);
        k_init<<<(unsigned)((total + 255) / 256), 256>>>(
            (const float4*)user_emb, (const float4*)item_emb);
    }

    // 3) three propagation layers (ping-pong, half buffers), acc fused
    const int spmm_blocks = (NODES + 7) / 8;
    k_spmm<0, false><<<spmm_blocks, 256>>>();   // layer 1: A -> B
    k_spmm<1, false><<<spmm_blocks, 256>>>();   // layer 2: B -> A
    k_spmm<0, true ><<<spmm_blocks, 256>>>();   // layer 3: A -> (acc only)

    // 4) readout
    k_dot<<<(BATCH + 7) / 8, 256>>>(users, items, gamma);
}

// round 8
// speedup vs baseline: 2.6067x; 1.5269x over previous
#include <cuda_runtime.h>
#include <cuda_fp16.h>
#include <cstdint>

#define USER_NUM 100000
#define ITEM_NUM 50000
#define NODES    150000            // USER_NUM + ITEM_NUM
#define D        256
#define NNZ      6400000
#define BATCH    16384
#define SCAN_BLK 256
#define NBLKS    ((NODES + SCAN_BLK - 1) / SCAN_BLK)   // 587

// ---------------------------------------------------------------------------
// Static device scratch
// ---------------------------------------------------------------------------
__device__ __align__(16) __half d_bufA[(size_t)NODES * D];  // emb (half)
__device__ __align__(16) __half d_bufB[(size_t)NODES * D];  // c1
__device__ __align__(16) __half d_bufC[(size_t)NODES * D];  // c2
__device__ float d_final[(size_t)2 * BATCH * D];            // sampled final rows

__device__ int  d_counts[NODES];
__device__ int  d_rowptr[NODES + 1];
__device__ int  d_fill  [NODES];
__device__ int  d_bsum  [NBLKS];
__device__ int2 d_edges [NNZ];          // .x = col, .y = val (float bits)

// ---------------------------------------------------------------------------
// CSR build
// ---------------------------------------------------------------------------
__global__ void k_zero_counts() {
    int i = blockIdx.x * blockDim.x + threadIdx.x;
    if (i < NODES) d_counts[i] = 0;
}

__global__ void k_histogram(const int* __restrict__ rows) {
    int e = blockIdx.x * blockDim.x + threadIdx.x;
    if (e < NNZ) atomicAdd(&d_counts[rows[e]], 1);
}

// Level 1: per-block sums of 256 counts
__global__ __launch_bounds__(SCAN_BLK) void k_blocksum() {
    __shared__ int sh[SCAN_BLK / 32];
    int i = blockIdx.x * SCAN_BLK + threadIdx.x;
    int v = (i < NODES) ? d_counts[i] : 0;
    int lane = threadIdx.x & 31, wid = threadIdx.x >> 5;
    #pragma unroll
    for (int o = 16; o > 0; o >>= 1) v += __shfl_down_sync(0xFFFFFFFFu, v, o);
    if (lane == 0) sh[wid] = v;
    __syncthreads();
    if (threadIdx.x == 0) {
        int s = 0;
        #pragma unroll
        for (int w = 0; w < SCAN_BLK / 32; ++w) s += sh[w];
        d_bsum[blockIdx.x] = s;
    }
}

// Level 2: exclusive scan of NBLKS partials in one block (NBLKS < 1024)
__global__ __launch_bounds__(1024) void k_scanbsum() {
    __shared__ int ws[32];
    int tid = threadIdx.x, lane = tid & 31, wid = tid >> 5;
    int v = (tid < NBLKS) ? d_bsum[tid] : 0;
    int x = v;
    #pragma unroll
    for (int o = 1; o < 32; o <<= 1) {
        int y = __shfl_up_sync(0xFFFFFFFFu, x, o);
        if (lane >= o) x += y;
    }
    if (lane == 31) ws[wid] = x;
    __syncthreads();
    if (tid < 32) {                    // full warp participates
        int w = ws[tid];
        #pragma unroll
        for (int o = 1; o < 32; o <<= 1) {
            int y = __shfl_up_sync(0xFFFFFFFFu, w, o);
            if (tid >= o) w += y;
        }
        ws[tid] = w;
    }
    __syncthreads();
    int off = (wid > 0) ? ws[wid - 1] : 0;
    if (tid < NBLKS) d_bsum[tid] = off + (x - v);     // exclusive
    if (tid == 1023) d_rowptr[NODES] = ws[31];        // total
}

// Level 3: per-block exclusive scan + block offset -> rowptr / fill
__global__ __launch_bounds__(SCAN_BLK) void k_rowptr() {
    __shared__ int ws[SCAN_BLK / 32];
    int i = blockIdx.x * SCAN_BLK + threadIdx.x;
    int lane = threadIdx.x & 31, wid = threadIdx.x >> 5;
    int v = (i < NODES) ? d_counts[i] : 0;
    int x = v;
    #pragma unroll
    for (int o = 1; o < 32; o <<= 1) {
        int y = __shfl_up_sync(0xFFFFFFFFu, x, o);
        if (lane >= o) x += y;
    }
    if (lane == 31) ws[wid] = x;
    __syncthreads();
    // Full warp runs the shuffle scan (8 live values padded with 0);
    // predicated-participation shuffles with a full-warp mask are UB.
    if (threadIdx.x < 32) {
        int w = (threadIdx.x < SCAN_BLK / 32) ? ws[threadIdx.x] : 0;
        #pragma unroll
        for (int o = 1; o < 32; o <<= 1) {
            int y = __shfl_up_sync(0xFFFFFFFFu, w, o);
            if ((int)threadIdx.x >= o) w += y;
        }
        if (threadIdx.x < SCAN_BLK / 32) ws[threadIdx.x] = w;
    }
    __syncthreads();
    int excl = d_bsum[blockIdx.x] + ((wid > 0) ? ws[wid - 1] : 0) + (x - v);
    if (i < NODES) {
        d_rowptr[i] = excl;
        d_fill[i]   = excl;
    }
}

__global__ void k_scatter(const int* __restrict__ rows,
                          const int* __restrict__ cols,
                          const float* __restrict__ vals) {
    int e = blockIdx.x * blockDim.x + threadIdx.x;
    if (e < NNZ) {
        int r = rows[e];
        int p = atomicAdd(&d_fill[r], 1);
        d_edges[p] = make_int2(cols[e], __float_as_int(vals[e]));
    }
}

// ---------------------------------------------------------------------------
// Init: bufA = concat(user_emb, item_emb) in half
// ---------------------------------------------------------------------------
__global__ void k_init(const float4* __restrict__ user_emb,
                       const float4* __restrict__ item_emb) {
    size_t i = (size_t)blockIdx.x * blockDim.x + threadIdx.x;  // 8-dim chunk
    const size_t total = (size_t)NODES * (D / 8);
    if (i >= total) return;
    size_t f4 = i * 2;
    const size_t user_f4 = (size_t)USER_NUM * (D / 4);
    float4 a, b;
    if (f4 < user_f4) { a = __ldg(user_emb + f4); b = __ldg(user_emb + f4 + 1); }
    else              { a = __ldg(item_emb + f4 - user_f4);
                        b = __ldg(item_emb + f4 + 1 - user_f4); }
    uint4 o;
    __half2 h;
    h = __floats2half2_rn(a.x, a.y); o.x = *(unsigned*)&h;
    h = __floats2half2_rn(a.z, a.w); o.y = *(unsigned*)&h;
    h = __floats2half2_rn(b.x, b.y); o.z = *(unsigned*)&h;
    h = __floats2half2_rn(b.z, b.w); o.w = *(unsigned*)&h;
    ((uint4*)d_bufA)[i] = o;
}

// ---------------------------------------------------------------------------
// Row gather core: accumulate sum_e val*in[col[e]] into a[8] (fp32)
// Warp per row; lane owns dims [lane*8, lane*8+8).
// ---------------------------------------------------------------------------
__device__ __forceinline__ void accum8(float* a, float w, uint4 v) {
    float2 f;
    f = __half22float2(*reinterpret_cast<__half2*>(&v.x));
    a[0] = fmaf(w, f.x, a[0]); a[1] = fmaf(w, f.y, a[1]);
    f = __half22float2(*reinterpret_cast<__half2*>(&v.y));
    a[2] = fmaf(w, f.x, a[2]); a[3] = fmaf(w, f.y, a[3]);
    f = __half22float2(*reinterpret_cast<__half2*>(&v.z));
    a[4] = fmaf(w, f.x, a[4]); a[5] = fmaf(w, f.y, a[5]);
    f = __half22float2(*reinterpret_cast<__half2*>(&v.w));
    a[6] = fmaf(w, f.x, a[6]); a[7] = fmaf(w, f.y, a[7]);
}

__device__ __forceinline__ void gather_row(const uint4* __restrict__ inb,
                                           int s, int e, int lane, float* a) {
    int k = s;
    for (; k + 4 <= e; k += 4) {
        int2 e0 = __ldg(&d_edges[k]);
        int2 e1 = __ldg(&d_edges[k + 1]);
        int2 e2 = __ldg(&d_edges[k + 2]);
        int2 e3 = __ldg(&d_edges[k + 3]);
        uint4 v0 = __ldg(inb + (size_t)e0.x * 32 + lane);
        uint4 v1 = __ldg(inb + (size_t)e1.x * 32 + lane);
        uint4 v2 = __ldg(inb + (size_t)e2.x * 32 + lane);
        uint4 v3 = __ldg(inb + (size_t)e3.x * 32 + lane);
        accum8(a, __int_as_float(e0.y), v0);
        accum8(a, __int_as_float(e1.y), v1);
        accum8(a, __int_as_float(e2.y), v2);
        accum8(a, __int_as_float(e3.y), v3);
    }
    for (; k < e; ++k) {
        int2 e0 = __ldg(&d_edges[k]);
        uint4 v0 = __ldg(inb + (size_t)e0.x * 32 + lane);
        accum8(a, __int_as_float(e0.y), v0);
    }
}

// Full SpMM layer: in -> out (half), all NODES rows. STAGE 0: A->B, 1: B->C.
template <int STAGE>
__global__ __launch_bounds__(256) void k_spmm() {
    const uint4* __restrict__ inb  = (const uint4*)((STAGE == 0) ? d_bufA : d_bufB);
    uint4*       __restrict__ outb = (uint4*)((STAGE == 0) ? d_bufB : d_bufC);

    int row = blockIdx.x * 8 + (threadIdx.x >> 5);
    if (row >= NODES) return;
    const int lane = threadIdx.x & 31;
    float a[8] = {0.f, 0.f, 0.f, 0.f, 0.f, 0.f, 0.f, 0.f};
    gather_row(inb, d_rowptr[row], d_rowptr[row + 1], lane, a);

    uint4 o;
    __half2 h;
    h = __floats2half2_rn(a[0], a[1]); o.x = *(unsigned*)&h;
    h = __floats2half2_rn(a[2], a[3]); o.y = *(unsigned*)&h;
    h = __floats2half2_rn(a[4], a[5]); o.z = *(unsigned*)&h;
    h = __floats2half2_rn(a[6], a[7]); o.w = *(unsigned*)&h;
    outb[(size_t)row * 32 + lane] = o;
}

// ---------------------------------------------------------------------------
// Final layer: ONLY sampled rows. j in [0, 2*BATCH):
//   j <  BATCH : row = users[j]
//   j >= BATCH : row = USER_NUM + items[j-BATCH]
// c3 = SpMM row over bufC; final = emb(fp32 inputs) + c1 + c2 + c3 -> d_final.
// ---------------------------------------------------------------------------
__global__ __launch_bounds__(256) void k_final(const float* __restrict__ user_emb,
                                               const float* __restrict__ item_emb,
                                               const int* __restrict__ users,
                                               const int* __restrict__ items) {
    int j = blockIdx.x * 8 + (threadIdx.x >> 5);
    if (j >= 2 * BATCH) return;
    const int lane = threadIdx.x & 31;
    int row = (j < BATCH) ? __ldg(users + j) : (USER_NUM + __ldg(items + j - BATCH));

    float a[8] = {0.f, 0.f, 0.f, 0.f, 0.f, 0.f, 0.f, 0.f};
    gather_row((const uint4*)d_bufC, d_rowptr[row], d_rowptr[row + 1], lane, a);

    // + c1 + c2 (half)
    uint4 h1 = __ldg((const uint4*)d_bufB + (size_t)row * 32 + lane);
    uint4 h2 = __ldg((const uint4*)d_bufC + (size_t)row * 32 + lane);
    accum8(a, 1.0f, h1);
    accum8(a, 1.0f, h2);

    // + emb (fp32 from inputs)
    const float4* embp = (row < USER_NUM)
        ? ((const float4*)user_emb + (size_t)row * 64 + lane * 2)
        : ((const float4*)item_emb + (size_t)(row - USER_NUM) * 64 + lane * 2);
    float4 e0 = __ldg(embp);
    float4 e1 = __ldg(embp + 1);
    a[0] += e0.x; a[1] += e0.y; a[2] += e0.z; a[3] += e0.w;
    a[4] += e1.x; a[5] += e1.y; a[6] += e1.z; a[7] += e1.w;

    float4* fp = (float4*)d_final + (size_t)j * 64 + lane * 2;
    fp[0] = make_float4(a[0], a[1], a[2], a[3]);
    fp[1] = make_float4(a[4], a[5], a[6], a[7]);
}

// ---------------------------------------------------------------------------
// Readout: gamma[b] = dot(final[b], final[BATCH+b]) / 16
// ---------------------------------------------------------------------------
__global__ __launch_bounds__(256) void k_dot(float* __restrict__ gamma) {
    int b = blockIdx.x * 8 + (threadIdx.x >> 5);
    if (b >= BATCH) return;
    const int lane = threadIdx.x & 31;

    const float4* pu = (const float4*)d_final + (size_t)b * 64 + lane * 2;
    const float4* pi = (const float4*)d_final + (size_t)(BATCH + b) * 64 + lane * 2;
    float4 u0 = pu[0], u1 = pu[1];
    float4 i0 = pi[0], i1 = pi[1];

    float s = u0.x * i0.x + u0.y * i0.y + u0.z * i0.z + u0.w * i0.w
            + u1.x * i1.x + u1.y * i1.y + u1.z * i1.z + u1.w * i1.w;
    #pragma unroll
    for (int o = 16; o > 0; o >>= 1)
        s += __shfl_down_sync(0xFFFFFFFFu, s, o);
    if (lane == 0) gamma[b] = s * (1.0f / 16.0f);   // (1/4)^2 from both means
}

// ---------------------------------------------------------------------------
// Launch
// ---------------------------------------------------------------------------
extern "C" void kernel_launch(void* const* d_in, const int* in_sizes, int n_in,
                              void* d_out, int out_size) {
    const float* user_emb = (const float*)d_in[0];   // [100000, 256]
    const float* item_emb = (const float*)d_in[1];   // [50000, 256]
    const float* vals     = (const float*)d_in[2];   // [NNZ]
    const int*   rows     = (const int*)  d_in[3];   // [NNZ]
    const int*   cols     = (const int*)  d_in[4];   // [NNZ]
    const int*   users    = (const int*)  d_in[5];   // [BATCH]
    const int*   items    = (const int*)  d_in[6];   // [BATCH]
    float*       gamma    = (float*)d_out;           // [BATCH]

    // 1) CSR build (two-level scan)
    k_zero_counts<<<(NODES + 255) / 256, 256>>>();
    k_histogram<<<(NNZ + 255) / 256, 256>>>(rows);
    k_blocksum<<<NBLKS, SCAN_BLK>>>();
    k_scanbsum<<<1, 1024>>>();
    k_rowptr<<<NBLKS, SCAN_BLK>>>();
    k_scatter<<<(NNZ + 255) / 256, 256>>>(rows, cols, vals);

    // 2) init bufA (half emb)
    {
        size_t total = (size_t)NODES * (D / 8);
        k_init<<<(unsigned)((total + 255) / 256), 256>>>(
            (const float4*)user_emb, (const float4*)item_emb);
    }

    // 3) layers 1-2 over all nodes; layer 3 only at sampled rows
    const int spmm_blocks = (NODES + 7) / 8;
    k_spmm<0><<<spmm_blocks, 256>>>();                    // c1 = A*emb  -> bufB
    k_spmm<1><<<spmm_blocks, 256>>>();                    // c2 = A*c1   -> bufC
    k_final<<<(2 * BATCH + 7) / 8, 256>>>(user_emb, item_emb, users, items);

    // 4) readout
    k_dot<<<(BATCH + 7) / 8, 256>>>(gamma);
}